// round 2
// baseline (speedup 1.0000x reference)
#include <cuda_runtime.h>
#include <cstdint>

#define NTPL 10
#define NACC 11                                   // 10 cross + 1 x·x
#define PIX 784
#define TILE_IMGS 32
#define CHUNKS 196                                // float4 chunks per image
#define STAGE_BYTES (TILE_IMGS * PIX * 4)         // 100352
#define TM_OFF (2 * STAGE_BYTES)                  // 200704 (templates, fp32)
#define TSQ_OFF (TM_OFF + NTPL * PIX * 4)         // 232064 (t_sq, 10 doubles)
#define SMEM_TOTAL (TSQ_OFF + 128)                // 232192 <= 232448 opt-in max

#define FMA2(acc, a, b) \
    asm("fma.rn.f32x2 %0, %1, %2, %0;" : "+l"(acc) : "l"(a), "l"(b))

// Stage one 32-image tile into shared memory, transposed to [chunk][img] 16B
// granules, via cp.async. Gmem side: consecutive threads read consecutive
// float4s within an image -> fully coalesced.
__device__ __forceinline__ void issue_tile(int tile, int ntiles, uint32_t sbase,
                                           const float4* __restrict__ xg4, int tid) {
    if (tile < ntiles) {
        const float4* src = xg4 + (size_t)tile * (TILE_IMGS * CHUNKS);
        #pragma unroll
        for (int r = 0; r < 25; r++) {
            int cid = tid + r * 256;
            if (cid < TILE_IMGS * CHUNKS) {
                uint32_t dst = sbase + (uint32_t)(cid % CHUNKS) * 512u
                                     + (uint32_t)(cid / CHUNKS) * 16u;
                asm volatile("cp.async.cg.shared.global [%0], [%1], 16;"
                             :: "r"(dst), "l"(src + cid));
            }
        }
    }
}

__global__ void __launch_bounds__(256, 1)
mse_argmin_kernel(const float* __restrict__ xg, const float* __restrict__ tg,
                  float* __restrict__ out, int ntiles) {
    extern __shared__ float sm[];
    const uint32_t smb = (uint32_t)__cvta_generic_to_shared(sm);
    const int tid = threadIdx.x;
    const int w = tid >> 5;
    const int lane = tid & 31;
    const int G = gridDim.x;
    const int t0 = blockIdx.x;
    const float4* xg4 = (const float4*)xg;

    // Prologue: get DRAM moving before anything else.
    issue_tile(t0, ntiles, smb + 0u, xg4, tid);
    asm volatile("cp.async.commit_group;" ::: "memory");
    issue_tile(t0 + G, ntiles, smb + STAGE_BYTES, xg4, tid);
    asm volatile("cp.async.commit_group;" ::: "memory");

    // Templates -> smem (once per block), then exact (fp64) squared norms.
    for (int i = tid; i < NTPL * PIX; i += 256) sm[(TM_OFF >> 2) + i] = tg[i];
    __syncthreads();
    double* tsq_d = (double*)(sm + (TSQ_OFF >> 2));
    if (tid < NTPL) {
        const float* tp = sm + (TM_OFF >> 2) + tid * PIX;
        double a = 0.0;
        for (int p = 0; p < PIX; p++) a = fma((double)tp[p], (double)tp[p], a);
        tsq_d[tid] = a;
    }
    __syncthreads();

    int stage = 0;
    for (int t = t0; t < ntiles; t += G, stage ^= 1) {
        const uint32_t soff = stage ? (uint32_t)STAGE_BYTES : 0u;
        const uint32_t sbase = smb + soff;

        asm volatile("cp.async.wait_group 1;" ::: "memory");
        __syncthreads();

        // ---- main loop: lane = image, warp covers chunks c = w, w+8, ... ----
        uint64_t acc[NACC];
        #pragma unroll
        for (int k = 0; k < NACC; k++) acc[k] = 0ull;

        uint32_t xaddr = sbase + (uint32_t)w * 512u + (uint32_t)lane * 16u;
        uint32_t taddr = smb + TM_OFF + (uint32_t)w * 16u;
        const int niter = (w < (CHUNKS & 7)) ? (CHUNKS / 8 + 1) : (CHUNKS / 8);
        #pragma unroll 2
        for (int i = 0; i < niter; i++) {
            uint64_t x01, x23;
            asm("ld.shared.v2.u64 {%0, %1}, [%2];"
                : "=l"(x01), "=l"(x23) : "r"(xaddr));
            #pragma unroll
            for (int k = 0; k < NTPL; k++) {
                uint64_t a01, a23;
                asm("ld.shared.v2.u64 {%0, %1}, [%2];"
                    : "=l"(a01), "=l"(a23) : "r"(taddr + (uint32_t)(k * PIX * 4)));
                FMA2(acc[k], x01, a01);
                FMA2(acc[k], x23, a23);
            }
            FMA2(acc[NTPL], x01, x01);       // x·x for the reference formula
            FMA2(acc[NTPL], x23, x23);
            xaddr += 8u * 512u;
            taddr += 8u * 16u;
        }
        __syncthreads();   // all warps done reading stage -> safe to reuse as scratch

        // ---- per-lane fold + per-warp fp32 partials into stage scratch ----
        float* red = sm + (soff >> 2);          // [k][warp][lane] : 11*8*32 floats
        #pragma unroll
        for (int k = 0; k < NACC; k++) {
            uint32_t lo, hi;
            asm("mov.b64 {%0, %1}, %2;" : "=r"(lo), "=r"(hi) : "l"(acc[k]));
            red[k * 256 + w * 32 + lane] = __uint_as_float(lo) + __uint_as_float(hi);
        }
        __syncthreads();

        // ---- cross-warp reduction in fp64: 352 (k,img) pairs over 256 thr ----
        double* dsum = (double*)(red + NACC * 256);   // [k][img] : 11*32 doubles
        for (int p = tid; p < NACC * TILE_IMGS; p += 256) {
            const int img = p & 31, k = p >> 5;
            double s = 0.0;
            #pragma unroll
            for (int ww = 0; ww < 8; ww++) s += (double)red[k * 256 + ww * 32 + img];
            dsum[k * 32 + img] = s;
        }
        __syncthreads();

        // ---- distances in fp64, rounded to fp32 exactly like the reference,
        //      then argmin (strict <, first index wins ties == jnp.argmin) ----
        if (tid < TILE_IMGS) {
            const double xx = dsum[NTPL * 32 + tid];
            float best = 0.f;
            int bi = 0;
            #pragma unroll
            for (int k = 0; k < NTPL; k++) {
                const double cross = dsum[k * 32 + tid];
                const float v = (float)((xx - 2.0 * cross + tsq_d[k]) / (double)PIX);
                if (k == 0 || v < best) { best = v; bi = k; }
            }
            out[(size_t)t * TILE_IMGS + tid] = (float)bi;
        }
        __syncthreads();   // scratch reads done before cp.async overwrites stage

        // ---- refill this stage with tile t+2G ----
        issue_tile(t + 2 * G, ntiles, sbase, xg4, tid);
        asm volatile("cp.async.commit_group;" ::: "memory");
    }
}

extern "C" void kernel_launch(void* const* d_in, const int* in_sizes, int n_in,
                              void* d_out, int out_size) {
    // Robust to input ordering: x is the big one.
    const float* a = (const float*)d_in[0];
    const float* b = (const float*)d_in[1];
    const float* xg;
    const float* tg;
    long nx;
    if (in_sizes[0] >= in_sizes[1]) { xg = a; tg = b; nx = in_sizes[0]; }
    else                            { xg = b; tg = a; nx = in_sizes[1]; }

    const int B = (int)(nx / PIX);
    const int ntiles = B / TILE_IMGS;   // 262144/32 = 8192, exact

    int dev = 0;
    cudaGetDevice(&dev);
    int nsm = 148;
    cudaDeviceGetAttribute(&nsm, cudaDevAttrMultiProcessorCount, dev);
    int grid = nsm < ntiles ? nsm : ntiles;

    cudaFuncSetAttribute(mse_argmin_kernel,
                         cudaFuncAttributeMaxDynamicSharedMemorySize, SMEM_TOTAL);

    mse_argmin_kernel<<<grid, 256, SMEM_TOTAL>>>(xg, tg, (float*)d_out, ntiles);
}